// round 3
// baseline (speedup 1.0000x reference)
#include <cuda_runtime.h>
#include <cstdint>

#define OUT_F  4096
#define IN_F   4096
#define NFREQ  10000
#define ROWS   1024          // 2 * 512
#define SCALE  2.34375f      // 150 / sqrt(4096)

// Scratch (static __device__ arrays — no allocation allowed)
static __device__ float    g_y[(size_t)ROWS * OUT_F];   // 16 MB: X·dense^T, then WHT'd
static __device__ unsigned g_key[NFREQ];
static __device__ int      g_valid[NFREQ];
static __device__ int      g_o[NFREQ];
static __device__ int      g_i[NFREQ];
static __device__ int      g_is32;

// ---------------------------------------------------------------------------
// 0) reset dtype flag (must be deterministic per replay)
__global__ void k_reset() {
    if (threadIdx.x == 0 && blockIdx.x == 0) g_is32 = 0;
}

// 0b) detect indices dtype. Reading NFREQ int64 = 80000 bytes, which is exactly
//     the buffer size under the int32 interpretation (2*NFREQ*4) — safe either way.
//     True int64 data: all values in [0, 4096). int32 data read as int64: high
//     word is the next index (nonzero w.p. 4095/4096) -> value >= 2^32.
__global__ void k_detect(const long long* __restrict__ idx) {
    int k = blockIdx.x * blockDim.x + threadIdx.x;
    if (k < NFREQ) {
        unsigned long long v = (unsigned long long)idx[k];
        if (v >= (unsigned long long)OUT_F) atomicOr(&g_is32, 1);
    }
}

// 1) decode (o, i) per entry under the detected dtype; pack dedupe keys.
__global__ void k_key(const void* __restrict__ idxv) {
    int k = blockIdx.x * blockDim.x + threadIdx.x;
    if (k >= NFREQ) return;
    int o, i;
    if (g_is32) {
        const int* p = (const int*)idxv;
        o = p[k];
        i = p[NFREQ + k];
    } else {
        const long long* p = (const long long*)idxv;
        o = (int)p[k];
        i = (int)p[NFREQ + k];
    }
    o &= (OUT_F - 1);                 // defensive: never index OOB
    i &= (IN_F - 1);
    g_o[k] = o;
    g_i[k] = i;
    g_key[k] = (unsigned)o * (unsigned)IN_F + (unsigned)i;
}

// 2) dedupe: entry k valid iff no LATER entry has the same (o,i)
//    (last update wins, matching sequential scatter .set semantics).
__global__ void k_dedupe() {
    int k = blockIdx.x * blockDim.x + threadIdx.x;
    if (k >= NFREQ) return;
    unsigned key = g_key[k];
    int v = 1;
    for (int j = k + 1; j < NFREQ; ++j) {
        if (g_key[j] == key) { v = 0; break; }
    }
    g_valid[k] = v;
}

// 3) zero y (must re-zero every graph replay)
__global__ void k_zero() {
    size_t t = (size_t)blockIdx.x * blockDim.x + threadIdx.x;
    reinterpret_cast<float4*>(g_y)[t] = make_float4(0.f, 0.f, 0.f, 0.f);
}

// 4) sparse contraction: y[r, o_k] += x[r, i_k] * s_k   for valid k
__global__ void k_scatter(const float* __restrict__ x,
                          const float* __restrict__ spec) {
    int k = blockIdx.y;
    if (!g_valid[k]) return;
    int r = blockIdx.x * blockDim.x + threadIdx.x;   // 0..1023
    int o = g_o[k];
    int i = g_i[k];
    float s = spec[k];
    atomicAdd(&g_y[(size_t)r * OUT_F + o], x[(size_t)r * IN_F + i] * s);
}

// 5) in-place 4096-pt Walsh-Hadamard transform along o, per row, then * SCALE.
//    Butterfly stages over distinct bits commute, so stage order matches iwht.
__global__ void k_wht() {
    __shared__ __align__(16) float s[OUT_F];
    int r = blockIdx.x;
    float* yr = g_y + (size_t)r * OUT_F;
    for (int j = threadIdx.x; j < OUT_F; j += blockDim.x) s[j] = yr[j];
    __syncthreads();
    for (int len = 1; len < OUT_F; len <<= 1) {
        for (int p = threadIdx.x; p < OUT_F / 2; p += blockDim.x) {
            int i0 = 2 * p - (p & (len - 1));
            int i1 = i0 + len;
            float a = s[i0], b = s[i1];
            s[i0] = a + b;
            s[i1] = a - b;
        }
        __syncthreads();
    }
    for (int j = threadIdx.x; j < OUT_F; j += blockDim.x) yr[j] = s[j] * SCALE;
}

// 6) GEMM (NT): out[r, o] = sum_i x[r,i] * w[o,i]  +  y_wht[r, o]
//    128x128 tile, BK=8, 256 threads, 8x8 microtile per thread.
__global__ __launch_bounds__(256)
void k_gemm(const float* __restrict__ x,
            const float* __restrict__ w,
            float* __restrict__ out) {
    __shared__ __align__(16) float Xs[8][128];
    __shared__ __align__(16) float Ws[8][128];

    const int bn = blockIdx.x;             // 0..31  (o tiles)
    const int bm = blockIdx.y;             // 0..7   (row tiles)
    const int tid = threadIdx.x;
    const int tx = tid & 15;               // n sub-tile
    const int ty = tid >> 4;               // m sub-tile

    const float* xg = x + (size_t)bm * 128 * IN_F;
    const float* wg = w + (size_t)bn * 128 * IN_F;

    const int lrow = tid >> 1;             // 0..127
    const int lcol = (tid & 1) * 4;        // 0 or 4

    float acc[8][8];
    #pragma unroll
    for (int m = 0; m < 8; ++m)
        #pragma unroll
        for (int n = 0; n < 8; ++n) acc[m][n] = 0.f;

    for (int kk = 0; kk < IN_F; kk += 8) {
        float4 xv = *reinterpret_cast<const float4*>(xg + (size_t)lrow * IN_F + kk + lcol);
        float4 wv = *reinterpret_cast<const float4*>(wg + (size_t)lrow * IN_F + kk + lcol);
        Xs[lcol + 0][lrow] = xv.x; Xs[lcol + 1][lrow] = xv.y;
        Xs[lcol + 2][lrow] = xv.z; Xs[lcol + 3][lrow] = xv.w;
        Ws[lcol + 0][lrow] = wv.x; Ws[lcol + 1][lrow] = wv.y;
        Ws[lcol + 2][lrow] = wv.z; Ws[lcol + 3][lrow] = wv.w;
        __syncthreads();

        #pragma unroll
        for (int k = 0; k < 8; ++k) {
            float xf[8], wf[8];
            *reinterpret_cast<float4*>(&xf[0]) = *reinterpret_cast<const float4*>(&Xs[k][ty * 8]);
            *reinterpret_cast<float4*>(&xf[4]) = *reinterpret_cast<const float4*>(&Xs[k][ty * 8 + 4]);
            *reinterpret_cast<float4*>(&wf[0]) = *reinterpret_cast<const float4*>(&Ws[k][tx * 8]);
            *reinterpret_cast<float4*>(&wf[4]) = *reinterpret_cast<const float4*>(&Ws[k][tx * 8 + 4]);
            #pragma unroll
            for (int m = 0; m < 8; ++m)
                #pragma unroll
                for (int n = 0; n < 8; ++n)
                    acc[m][n] = fmaf(xf[m], wf[n], acc[m][n]);
        }
        __syncthreads();
    }

    const int r0 = bm * 128 + ty * 8;
    const int c0 = bn * 128 + tx * 8;
    #pragma unroll
    for (int m = 0; m < 8; ++m) {
        size_t base = (size_t)(r0 + m) * OUT_F + c0;
        #pragma unroll
        for (int nq = 0; nq < 2; ++nq) {
            float4 yv = *reinterpret_cast<const float4*>(&g_y[base + nq * 4]);
            float4 ov;
            ov.x = acc[m][nq * 4 + 0] + yv.x;
            ov.y = acc[m][nq * 4 + 1] + yv.y;
            ov.z = acc[m][nq * 4 + 2] + yv.z;
            ov.w = acc[m][nq * 4 + 3] + yv.w;
            *reinterpret_cast<float4*>(&out[base + nq * 4]) = ov;
        }
    }
}

// ---------------------------------------------------------------------------
extern "C" void kernel_launch(void* const* d_in, const int* in_sizes, int n_in,
                              void* d_out, int out_size) {
    const float* x    = (const float*)d_in[0];   // [2,512,4096]
    const float* w    = (const float*)d_in[1];   // [4096,4096]
    const float* spec = (const float*)d_in[2];   // [10000]
    const void*  idx  = d_in[3];                 // [2,10000] int32 or int64
    float* out = (float*)d_out;                  // [2,512,4096]
    (void)in_sizes; (void)n_in; (void)out_size;

    k_reset <<<1, 32>>>();
    k_detect<<<(NFREQ + 255) / 256, 256>>>((const long long*)idx);
    k_key   <<<(NFREQ + 255) / 256, 256>>>(idx);
    k_dedupe<<<(NFREQ + 255) / 256, 256>>>();
    k_zero  <<<((size_t)ROWS * OUT_F / 4) / 256, 256>>>();
    k_scatter<<<dim3(ROWS / 256, NFREQ), 256>>>(x, spec);
    k_wht   <<<ROWS, 256>>>();
    k_gemm  <<<dim3(OUT_F / 128, ROWS / 128), 256>>>(x, w, out);
}

// round 4
// speedup vs baseline: 1.0009x; 1.0009x over previous
#include <cuda_runtime.h>
#include <cstdint>

#define OUT_F  4096
#define IN_F   4096
#define NFREQ  10000
#define ROWS   1024          // 2 * 512
#define SCALE  2.34375f      // 150 / sqrt(4096)

// Scratch (static __device__ arrays — no allocation allowed)
static __device__ float    g_y[(size_t)ROWS * OUT_F];   // 16 MB: X·dense^T, then WHT'd
static __device__ unsigned g_key[NFREQ];
static __device__ int      g_valid[NFREQ];
static __device__ int      g_o[NFREQ];
static __device__ int      g_i[NFREQ];
static __device__ int      g_is32;

// ---------------------------------------------------------------------------
// 0) reset dtype flag (must be deterministic per replay)
__global__ void k_reset() {
    if (threadIdx.x == 0 && blockIdx.x == 0) g_is32 = 0;
}

// 0b) detect indices dtype. Reading NFREQ int64 = 80000 bytes, which is exactly
//     the buffer size under the int32 interpretation (2*NFREQ*4) — safe either way.
//     True int64 data: all values in [0, 4096). int32 data read as int64: high
//     word is the next index (nonzero w.p. 4095/4096) -> value >= 2^32.
__global__ void k_detect(const long long* __restrict__ idx) {
    int k = blockIdx.x * blockDim.x + threadIdx.x;
    if (k < NFREQ) {
        unsigned long long v = (unsigned long long)idx[k];
        if (v >= (unsigned long long)OUT_F) atomicOr(&g_is32, 1);
    }
}

// 1) decode (o, i) per entry under the detected dtype; pack dedupe keys.
__global__ void k_key(const void* __restrict__ idxv) {
    int k = blockIdx.x * blockDim.x + threadIdx.x;
    if (k >= NFREQ) return;
    int o, i;
    if (g_is32) {
        const int* p = (const int*)idxv;
        o = p[k];
        i = p[NFREQ + k];
    } else {
        const long long* p = (const long long*)idxv;
        o = (int)p[k];
        i = (int)p[NFREQ + k];
    }
    o &= (OUT_F - 1);                 // defensive: never index OOB
    i &= (IN_F - 1);
    g_o[k] = o;
    g_i[k] = i;
    g_key[k] = (unsigned)o * (unsigned)IN_F + (unsigned)i;
}

// 2) dedupe: entry k valid iff no LATER entry has the same (o,i)
//    (last update wins, matching sequential scatter .set semantics).
__global__ void k_dedupe() {
    int k = blockIdx.x * blockDim.x + threadIdx.x;
    if (k >= NFREQ) return;
    unsigned key = g_key[k];
    int v = 1;
    for (int j = k + 1; j < NFREQ; ++j) {
        if (g_key[j] == key) { v = 0; break; }
    }
    g_valid[k] = v;
}

// 3) zero y (must re-zero every graph replay)
__global__ void k_zero() {
    size_t t = (size_t)blockIdx.x * blockDim.x + threadIdx.x;
    reinterpret_cast<float4*>(g_y)[t] = make_float4(0.f, 0.f, 0.f, 0.f);
}

// 4) sparse contraction: y[r, o_k] += x[r, i_k] * s_k   for valid k
__global__ void k_scatter(const float* __restrict__ x,
                          const float* __restrict__ spec) {
    int k = blockIdx.y;
    if (!g_valid[k]) return;
    int r = blockIdx.x * blockDim.x + threadIdx.x;   // 0..1023
    int o = g_o[k];
    int i = g_i[k];
    float s = spec[k];
    atomicAdd(&g_y[(size_t)r * OUT_F + o], x[(size_t)r * IN_F + i] * s);
}

// 5) in-place 4096-pt Walsh-Hadamard transform along o, per row, then * SCALE.
//    Butterfly stages over distinct bits commute, so stage order matches iwht.
__global__ void k_wht() {
    __shared__ __align__(16) float s[OUT_F];
    int r = blockIdx.x;
    float* yr = g_y + (size_t)r * OUT_F;
    for (int j = threadIdx.x; j < OUT_F; j += blockDim.x) s[j] = yr[j];
    __syncthreads();
    for (int len = 1; len < OUT_F; len <<= 1) {
        for (int p = threadIdx.x; p < OUT_F / 2; p += blockDim.x) {
            int i0 = 2 * p - (p & (len - 1));
            int i1 = i0 + len;
            float a = s[i0], b = s[i1];
            s[i0] = a + b;
            s[i1] = a - b;
        }
        __syncthreads();
    }
    for (int j = threadIdx.x; j < OUT_F; j += blockDim.x) yr[j] = s[j] * SCALE;
}

// 6) GEMM (NT): out[r, o] = sum_i x[r,i] * w[o,i]  +  y_wht[r, o]
//    128x128 tile, BK=8, 256 threads, 8x8 microtile per thread.
__global__ __launch_bounds__(256)
void k_gemm(const float* __restrict__ x,
            const float* __restrict__ w,
            float* __restrict__ out) {
    __shared__ __align__(16) float Xs[8][128];
    __shared__ __align__(16) float Ws[8][128];

    const int bn = blockIdx.x;             // 0..31  (o tiles)
    const int bm = blockIdx.y;             // 0..7   (row tiles)
    const int tid = threadIdx.x;
    const int tx = tid & 15;               // n sub-tile
    const int ty = tid >> 4;               // m sub-tile

    const float* xg = x + (size_t)bm * 128 * IN_F;
    const float* wg = w + (size_t)bn * 128 * IN_F;

    const int lrow = tid >> 1;             // 0..127
    const int lcol = (tid & 1) * 4;        // 0 or 4

    float acc[8][8];
    #pragma unroll
    for (int m = 0; m < 8; ++m)
        #pragma unroll
        for (int n = 0; n < 8; ++n) acc[m][n] = 0.f;

    for (int kk = 0; kk < IN_F; kk += 8) {
        float4 xv = *reinterpret_cast<const float4*>(xg + (size_t)lrow * IN_F + kk + lcol);
        float4 wv = *reinterpret_cast<const float4*>(wg + (size_t)lrow * IN_F + kk + lcol);
        Xs[lcol + 0][lrow] = xv.x; Xs[lcol + 1][lrow] = xv.y;
        Xs[lcol + 2][lrow] = xv.z; Xs[lcol + 3][lrow] = xv.w;
        Ws[lcol + 0][lrow] = wv.x; Ws[lcol + 1][lrow] = wv.y;
        Ws[lcol + 2][lrow] = wv.z; Ws[lcol + 3][lrow] = wv.w;
        __syncthreads();

        #pragma unroll
        for (int k = 0; k < 8; ++k) {
            float xf[8], wf[8];
            *reinterpret_cast<float4*>(&xf[0]) = *reinterpret_cast<const float4*>(&Xs[k][ty * 8]);
            *reinterpret_cast<float4*>(&xf[4]) = *reinterpret_cast<const float4*>(&Xs[k][ty * 8 + 4]);
            *reinterpret_cast<float4*>(&wf[0]) = *reinterpret_cast<const float4*>(&Ws[k][tx * 8]);
            *reinterpret_cast<float4*>(&wf[4]) = *reinterpret_cast<const float4*>(&Ws[k][tx * 8 + 4]);
            #pragma unroll
            for (int m = 0; m < 8; ++m)
                #pragma unroll
                for (int n = 0; n < 8; ++n)
                    acc[m][n] = fmaf(xf[m], wf[n], acc[m][n]);
        }
        __syncthreads();
    }

    const int r0 = bm * 128 + ty * 8;
    const int c0 = bn * 128 + tx * 8;
    #pragma unroll
    for (int m = 0; m < 8; ++m) {
        size_t base = (size_t)(r0 + m) * OUT_F + c0;
        #pragma unroll
        for (int nq = 0; nq < 2; ++nq) {
            float4 yv = *reinterpret_cast<const float4*>(&g_y[base + nq * 4]);
            float4 ov;
            ov.x = acc[m][nq * 4 + 0] + yv.x;
            ov.y = acc[m][nq * 4 + 1] + yv.y;
            ov.z = acc[m][nq * 4 + 2] + yv.z;
            ov.w = acc[m][nq * 4 + 3] + yv.w;
            *reinterpret_cast<float4*>(&out[base + nq * 4]) = ov;
        }
    }
}

// ---------------------------------------------------------------------------
extern "C" void kernel_launch(void* const* d_in, const int* in_sizes, int n_in,
                              void* d_out, int out_size) {
    const float* x    = (const float*)d_in[0];   // [2,512,4096]
    const float* w    = (const float*)d_in[1];   // [4096,4096]
    const float* spec = (const float*)d_in[2];   // [10000]
    const void*  idx  = d_in[3];                 // [2,10000] int32 or int64
    float* out = (float*)d_out;                  // [2,512,4096]
    (void)in_sizes; (void)n_in; (void)out_size;

    k_reset <<<1, 32>>>();
    k_detect<<<(NFREQ + 255) / 256, 256>>>((const long long*)idx);
    k_key   <<<(NFREQ + 255) / 256, 256>>>(idx);
    k_dedupe<<<(NFREQ + 255) / 256, 256>>>();
    k_zero  <<<((size_t)ROWS * OUT_F / 4) / 256, 256>>>();
    k_scatter<<<dim3(ROWS / 256, NFREQ), 256>>>(x, spec);
    k_wht   <<<ROWS, 256>>>();
    k_gemm  <<<dim3(OUT_F / 128, ROWS / 128), 256>>>(x, w, out);
}